// round 11
// baseline (speedup 1.0000x reference)
#include <cuda_runtime.h>
#include <math_constants.h>

// ProbAttention: B=4, L=4096, H=8, D=64, FACTOR=5
#define B_ 4
#define L_ 4096
#define H_ 8
#define D_ 64
#define SK_ 45
#define U_  45
#define NSPLIT 64
#define KC 64          // keys per split = L_/NSPLIT
#define PADK 68
#define NCH 4          // key chunks for chunked-gather M (1024 keys each)

// Scratch (device globals; no allocation allowed)
__device__ int   g_Mtop[B_ * H_ * U_];
__device__ float g_vmean[B_ * H_ * D_];
__device__ float g_pm[B_ * H_ * NSPLIT * U_];
__device__ float g_ps[B_ * H_ * NSPLIT * U_];
__device__ float g_pacc[B_ * H_ * NSPLIT * U_ * D_];   // 23.6 MB
__device__ int   g_blist[L_ * SK_];           // sample ids grouped by chunk
__device__ int   g_boff[L_ * (NCH + 1)];      // per-query chunk offsets
__device__ float g_pmax[NCH * B_ * H_ * L_];  // 2 MB
__device__ float g_psum[NCH * B_ * H_ * L_];  // 2 MB

typedef unsigned long long ull;
__device__ __forceinline__ float lo2(ull v) { return __uint_as_float((unsigned)v); }
__device__ __forceinline__ float hi2(ull v) { return __uint_as_float((unsigned)(v >> 32)); }
#define FMA2(acc, a, b) asm("fma.rn.f32x2 %0, %1, %2, %0;" : "+l"(acc) : "l"(a), "l"(b))
#define DUP2(out, x) asm("mov.b64 %0, {%1, %1};" : "=l"(out) : "r"(__float_as_uint(x)))

__device__ __forceinline__ unsigned smem_u32(const void* p) {
    return (unsigned)__cvta_generic_to_shared(p);
}

// ---------------------------------------------------------------------------
// Kernel A: bucket sample indices into NCH=4 key chunks (+ zero vmean).
// 16 blocks x 256 threads; one thread per query l.
// ---------------------------------------------------------------------------
__global__ void __launch_bounds__(256) kernel_bucket(const int* __restrict__ idx) {
    int t = threadIdx.x;
    int l = blockIdx.x * 256 + t;
    int cnt[NCH + 1];
#pragma unroll
    for (int c = 0; c <= NCH; c++) cnt[c] = 0;
    const int* ip = idx + l * SK_;
    int samp[SK_];
#pragma unroll 5
    for (int s = 0; s < SK_; s++) { samp[s] = ip[s]; cnt[samp[s] >> 10]++; }
    int acc = 0;
#pragma unroll
    for (int c = 0; c < NCH; c++) {
        int v = cnt[c];
        g_boff[l * (NCH + 1) + c] = acc;
        cnt[c] = acc;
        acc += v;
    }
    g_boff[l * (NCH + 1) + NCH] = SK_;
#pragma unroll 5
    for (int s = 0; s < SK_; s++) {
        int v = samp[s];
        int c = v >> 10;
        g_blist[l * SK_ + cnt[c]++] = v;
    }
    if (blockIdx.x == 0)
        for (int i = t; i < B_ * H_ * D_; i += 256) g_vmean[i] = 0.0f;
}

// ---------------------------------------------------------------------------
// Kernel B: chunked-gather M. grid = 128 blocks (c = x&3, bh = x>>2),
// 1024 threads, 1 block/SM (reg-limited). The block's 256 KB K chunk
// becomes L1-resident; Q/blist/boff use streaming (__ldcs) loads so they
// don't pollute it. Warp structure identical to the proven gather kernel:
// 8-lane row groups, 4 samples in flight.
// ---------------------------------------------------------------------------
__global__ void __launch_bounds__(1024, 1) kernel_M3(const float* __restrict__ Q,
                                                     const float* __restrict__ K) {
    int blk = blockIdx.x;
    int c = blk & 3;
    int bh = blk >> 2;
    int h = bh & 7, b = bh >> 3;
    int warp = threadIdx.x >> 5;          // 0..31
    int lane = threadIdx.x & 31;
    int li = lane & 7;                    // lane within 8-lane row group
    int g  = lane >> 3;                   // sample group 0..3

    float* pmax = g_pmax + ((c << 5) + bh) * L_;
    float* psum = g_psum + ((c << 5) + bh) * L_;

    for (int i = 0; i < 128; i++) {
        int l = warp * 128 + i;
        const float4* q4 = (const float4*)(Q + ((size_t)(b * L_ + l) * H_ + h) * D_);
        float4 qa = __ldcs(q4 + li * 2);
        float4 qb = __ldcs(q4 + li * 2 + 1);

        int st = __ldcs(&g_boff[l * (NCH + 1) + c]);
        int en = __ldcs(&g_boff[l * (NCH + 1) + c + 1]);

        float mx = -CUDART_INF_F, sm = 0.0f;
        for (int r = st; r < en; r += 4) {
            int s = r + g;
            bool valid = (s < en);
            int kr = __ldcs(&g_blist[l * SK_ + (valid ? s : st)]);
            const float4* k4 = (const float4*)(K + ((size_t)(b * L_ + kr) * H_ + h) * D_);
            float4 ka = __ldg(k4 + li * 2);
            float4 kb = __ldg(k4 + li * 2 + 1);
            float d = qa.x * ka.x + qa.y * ka.y + qa.z * ka.z + qa.w * ka.w
                    + qb.x * kb.x + qb.y * kb.y + qb.z * kb.z + qb.w * kb.w;
            d += __shfl_xor_sync(0xffffffffu, d, 4);
            d += __shfl_xor_sync(0xffffffffu, d, 2);
            d += __shfl_xor_sync(0xffffffffu, d, 1);
            if (valid) { mx = fmaxf(mx, d); sm += d; }
        }
        mx = fmaxf(mx, __shfl_xor_sync(0xffffffffu, mx, 8));
        mx = fmaxf(mx, __shfl_xor_sync(0xffffffffu, mx, 16));
        sm += __shfl_xor_sync(0xffffffffu, sm, 8);
        sm += __shfl_xor_sync(0xffffffffu, sm, 16);
        if (lane == 0) { pmax[l] = mx; psum[l] = sm; }
    }
}

// ---------------------------------------------------------------------------
// Kernel 2: top-U per (b,h): fold NCH chunk partials -> M keys, then
// two-level radix histogram + exact tail select.
// ---------------------------------------------------------------------------
__device__ __forceinline__ unsigned f2key(float f) {
    unsigned u = __float_as_uint(f);
    return (u & 0x80000000u) ? ~u : (u | 0x80000000u);
}

__global__ void __launch_bounds__(256) kernel_topk() {
    __shared__ unsigned skeys[L_];
    __shared__ int hist[256];
    __shared__ unsigned candKey[1024];
    __shared__ int candIdx[1024];
    __shared__ int sT1, sN1, sT2;
    __shared__ int cSel, cCand;
    __shared__ unsigned rk[256];
    __shared__ int ri[256];

    int bh = blockIdx.x;
    int t = threadIdx.x;
    for (int i = t; i < L_; i += 256) {
        float mx = -CUDART_INF_F, sm = 0.0f;
#pragma unroll
        for (int c = 0; c < NCH; c++) {
            mx = fmaxf(mx, g_pmax[((c << 5) + bh) * L_ + i]);
            sm += g_psum[((c << 5) + bh) * L_ + i];
        }
        skeys[i] = f2key(mx - sm * (1.0f / (float)L_));
    }
    hist[t] = 0;
    __syncthreads();

    for (int i = t; i < L_; i += 256) atomicAdd(&hist[skeys[i] >> 24], 1);
    __syncthreads();
    if (t == 0) {
        int acc = 0;
        for (int bin = 255; bin >= 0; bin--) {
            if (acc + hist[bin] >= U_) { sT1 = bin; sN1 = acc; break; }
            acc += hist[bin];
        }
    }
    __syncthreads();
    int T1 = sT1, n1 = sN1;
    hist[t] = 0;
    __syncthreads();

    for (int i = t; i < L_; i += 256)
        if ((int)(skeys[i] >> 24) == T1) atomicAdd(&hist[(skeys[i] >> 16) & 255], 1);
    __syncthreads();
    if (t == 0) {
        int acc = n1;
        for (int bin = 255; bin >= 0; bin--) {
            if (acc + hist[bin] >= U_) { sT2 = bin; break; }
            acc += hist[bin];
        }
        cSel = 0; cCand = 0;
    }
    __syncthreads();
    unsigned TH16 = ((unsigned)T1 << 8) | (unsigned)sT2;

    for (int i = t; i < L_; i += 256) {
        unsigned k16 = skeys[i] >> 16;
        if (k16 > TH16) {
            int pos = atomicAdd(&cSel, 1);
            g_Mtop[bh * U_ + pos] = i;
        } else if (k16 == TH16) {
            int pos = atomicAdd(&cCand, 1);
            if (pos < 1024) { candKey[pos] = skeys[i]; candIdx[pos] = i; }
        }
    }
    __syncthreads();
    int ndef = cSel;
    int need = U_ - ndef;
    int nc = (cCand < 1024) ? cCand : 1024;

    for (int it = 0; it < need; it++) {
        unsigned best = 0; int bi = -1;
        for (int jj = t; jj < nc; jj += 256) {
            unsigned v = candKey[jj];
            if (v > best) { best = v; bi = jj; }
        }
        rk[t] = best; ri[t] = bi;
        __syncthreads();
        for (int s = 128; s; s >>= 1) {
            if (t < s && rk[t + s] > rk[t]) { rk[t] = rk[t + s]; ri[t] = ri[t + s]; }
            __syncthreads();
        }
        if (t == 0) {
            g_Mtop[bh * U_ + ndef + it] = candIdx[ri[0]];
            candKey[ri[0]] = 0;
        }
        __syncthreads();
    }
}

// ---------------------------------------------------------------------------
// Kernel 3: V mean partial sums (vmean zeroed by kernel_bucket)
// ---------------------------------------------------------------------------
__global__ void __launch_bounds__(256) kernel_mean_part(const float* __restrict__ V) {
    int blk = blockIdx.x;              // 1024 blocks
    int seg = blk & 31;
    int bh = blk >> 5;
    int h = bh & (H_ - 1);
    int b = bh >> 3;
    int t = threadIdx.x;
    int d4 = t & 15;
    int sub = t >> 4;
    int l0 = seg * 128;
    const float4* V4 = (const float4*)V;
    float ax = 0.f, ay = 0.f, az = 0.f, aw = 0.f;
#pragma unroll
    for (int i = 0; i < 8; i++) {
        int l = l0 + sub + i * 16;
        float4 v = V4[((size_t)(b * L_ + l) * H_ + h) * 16 + d4];
        ax += v.x; ay += v.y; az += v.z; aw += v.w;
    }
    __shared__ float4 s[16][16];
    s[sub][d4] = make_float4(ax, ay, az, aw);
    __syncthreads();
    if (t < 16) {
        float tx = 0.f, ty = 0.f, tz = 0.f, tw = 0.f;
#pragma unroll
        for (int jj = 0; jj < 16; jj++) {
            float4 v = s[jj][t];
            tx += v.x; ty += v.y; tz += v.z; tw += v.w;
        }
        atomicAdd(&g_vmean[bh * D_ + t * 4 + 0], tx);
        atomicAdd(&g_vmean[bh * D_ + t * 4 + 1], ty);
        atomicAdd(&g_vmean[bh * D_ + t * 4 + 2], tz);
        atomicAdd(&g_vmean[bh * D_ + t * 4 + 3], tw);
    }
}

// ---------------------------------------------------------------------------
// Kernel 4: fill out with V-mean broadcast (float4 stores)
// ---------------------------------------------------------------------------
__global__ void kernel_fill(float* __restrict__ out) {
    unsigned i = blockIdx.x * blockDim.x + threadIdx.x;  // float4 index
    int d4 = i & 15;
    int h = (i >> 4) & 7;
    int b = i >> 19;
    const float4* vm4 = (const float4*)g_vmean;
    float4 v = vm4[(b * H_ + h) * 16 + d4];
    const float inv = 1.0f / (float)L_;
    ((float4*)out)[i] = make_float4(v.x * inv, v.y * inv, v.z * inv, v.w * inv);
}

// ---------------------------------------------------------------------------
// Kernel 5: split-KV attention (NSPLIT=64, KC=64), float2 q/e loads.
// ---------------------------------------------------------------------------
#define OFF_V   (64 * PADK)
#define OFF_QE  (OFF_V + 64 * PADK)
#define OFF_MT  (OFF_QE + 48 * 64)
#define SMEM_FLOATS (OFF_MT + 64)
#define SMEM_BYTES  (SMEM_FLOATS * 4)

__global__ void __launch_bounds__(256) kernel_attn_part(
        const float* __restrict__ Q,
        const float* __restrict__ K,
        const float* __restrict__ V) {
    extern __shared__ float smem[];
    float* sKT = smem;                  // [64][PADK]  K transposed [d][k]
    float* sV  = smem + OFF_V;          // [64][PADK]  V natural   [k][d]
    float* sQE = smem + OFF_QE;         // [48][64]    Q rows, then E rows
    int*   sMt = (int*)(smem + OFF_MT);

    int bh = blockIdx.x >> 6;
    int sp = blockIdx.x & 63;
    int h = bh & 7, b = bh >> 3;
    int k0 = sp * KC;
    int t = threadIdx.x;

    {
        const char* vbase = (const char*)(V + ((size_t)(b * L_ + k0) * H_ + h) * D_);
#pragma unroll
        for (int i = 0; i < 4; i++) {
            int e = t + i * 256;
            int row = e >> 4, c = e & 15;
            unsigned dst = smem_u32(sV + row * PADK + c * 4);
            const char* src = vbase + (size_t)row * (H_ * D_ * 4) + c * 16;
            asm volatile("cp.async.cg.shared.global [%0], [%1], 16;"
                         :: "r"(dst), "l"(src));
        }
        asm volatile("cp.async.commit_group;");
    }

    if (t < U_) sMt[t] = g_Mtop[bh * U_ + t];
    __syncthreads();

#pragma unroll
    for (int i = 0; i < 3; i++) {
        int e = t + i * 256;
        int u = e >> 4, c = e & 15;
        float4 q = make_float4(0.f, 0.f, 0.f, 0.f);
        if (u < U_)
            q = *(const float4*)(Q + ((b * L_ + sMt[u]) * H_ + h) * D_ + c * 4);
        *(float4*)(sQE + u * 64 + c * 4) = q;
    }
#pragma unroll
    for (int i = 0; i < 16; i++) {
        int e = t + i * 256;
        int k = e >> 6, d = e & 63;
        sKT[d * PADK + k] = K[((b * L_ + k0 + k) * H_ + h) * D_ + d];
    }
    __syncthreads();

    int kt = t & 15, ut = t >> 4;
    int kk = kt * 4, u0 = ut * 3;

    ull a00 = 0, a01 = 0, a10 = 0, a11 = 0, a20 = 0, a21 = 0;
    {
        const float* q0p = sQE + (u0 + 0) * 64;
        const float* q1p = sQE + (u0 + 1) * 64;
        const float* q2p = sQE + (u0 + 2) * 64;
#pragma unroll 4
        for (int d = 0; d < 64; d += 2) {
            ulonglong2 kva = *(const ulonglong2*)&sKT[d * PADK + kk];
            ulonglong2 kvb = *(const ulonglong2*)&sKT[(d + 1) * PADK + kk];
            float2 f0 = *(const float2*)(q0p + d);
            float2 f1 = *(const float2*)(q1p + d);
            float2 f2 = *(const float2*)(q2p + d);
            ull q0a, q0b, q1a, q1b, q2a, q2b;
            DUP2(q0a, f0.x); DUP2(q0b, f0.y);
            DUP2(q1a, f1.x); DUP2(q1b, f1.y);
            DUP2(q2a, f2.x); DUP2(q2b, f2.y);
            FMA2(a00, q0a, kva.x); FMA2(a01, q0a, kva.y);
            FMA2(a10, q1a, kva.x); FMA2(a11, q1a, kva.y);
            FMA2(a20, q2a, kva.x); FMA2(a21, q2a, kva.y);
            FMA2(a00, q0b, kvb.x); FMA2(a01, q0b, kvb.y);
            FMA2(a10, q1b, kvb.x); FMA2(a11, q1b, kvb.y);
            FMA2(a20, q2b, kvb.x); FMA2(a21, q2b, kvb.y);
        }
    }

    float ev[3][4];
    {
        const float sc = 0.125f;
        ull ra[3][2] = {{a00, a01}, {a10, a11}, {a20, a21}};
#pragma unroll
        for (int jj = 0; jj < 3; jj++) {
            float s0 = lo2(ra[jj][0]) * sc, s1 = hi2(ra[jj][0]) * sc;
            float s2 = lo2(ra[jj][1]) * sc, s3 = hi2(ra[jj][1]) * sc;
            float mm = fmaxf(fmaxf(s0, s1), fmaxf(s2, s3));
            mm = fmaxf(mm, __shfl_xor_sync(0xffffffffu, mm, 1));
            mm = fmaxf(mm, __shfl_xor_sync(0xffffffffu, mm, 2));
            mm = fmaxf(mm, __shfl_xor_sync(0xffffffffu, mm, 4));
            mm = fmaxf(mm, __shfl_xor_sync(0xffffffffu, mm, 8));
            float e0 = __expf(s0 - mm), e1 = __expf(s1 - mm);
            float e2 = __expf(s2 - mm), e3 = __expf(s3 - mm);
            float ss = (e0 + e1) + (e2 + e3);
            ss += __shfl_xor_sync(0xffffffffu, ss, 1);
            ss += __shfl_xor_sync(0xffffffffu, ss, 2);
            ss += __shfl_xor_sync(0xffffffffu, ss, 4);
            ss += __shfl_xor_sync(0xffffffffu, ss, 8);
            ev[jj][0] = e0; ev[jj][1] = e1; ev[jj][2] = e2; ev[jj][3] = e3;
            int u = u0 + jj;
            if (kt == 0 && u < U_) {
                g_pm[(bh * NSPLIT + sp) * U_ + u] = mm;
                g_ps[(bh * NSPLIT + sp) * U_ + u] = ss;
            }
        }
    }
    __syncthreads();

#pragma unroll
    for (int jj = 0; jj < 3; jj++)
        *(float4*)(sQE + (u0 + jj) * 64 + kk) =
            make_float4(ev[jj][0], ev[jj][1], ev[jj][2], ev[jj][3]);

    asm volatile("cp.async.wait_group 0;");
    __syncthreads();

    {
        int dd = kk;
        ull c00 = 0, c01 = 0, c10 = 0, c11 = 0, c20 = 0, c21 = 0;
        const float* e0p = sQE + (u0 + 0) * 64;
        const float* e1p = sQE + (u0 + 1) * 64;
        const float* e2p = sQE + (u0 + 2) * 64;
#pragma unroll 4
        for (int k = 0; k < 64; k += 2) {
            ulonglong2 vva = *(const ulonglong2*)&sV[k * PADK + dd];
            ulonglong2 vvb = *(const ulonglong2*)&sV[(k + 1) * PADK + dd];
            float2 f0 = *(const float2*)(e0p + k);
            float2 f1 = *(const float2*)(e1p + k);
            float2 f2 = *(const float2*)(e2p + k);
            ull e0a, e0b, e1a, e1b, e2a, e2b;
            DUP2(e0a, f0.x); DUP2(e0b, f0.y);
            DUP2(e1a, f1.x); DUP2(e1b, f1.y);
            DUP2(e2a, f2.x); DUP2(e2b, f2.y);
            FMA2(c00, e0a, vva.x); FMA2(c01, e0a, vva.y);
            FMA2(c10, e1a, vva.x); FMA2(c11, e1a, vva.y);
            FMA2(c20, e2a, vva.x); FMA2(c21, e2a, vva.y);
            FMA2(c00, e0b, vvb.x); FMA2(c01, e0b, vvb.y);
            FMA2(c10, e1b, vvb.x); FMA2(c11, e1b, vvb.y);
            FMA2(c20, e2b, vvb.x); FMA2(c21, e2b, vvb.y);
        }
        float* pa = g_pacc + (size_t)(bh * NSPLIT + sp) * U_ * D_;
        if (u0 + 0 < U_)
            *(float4*)&pa[(u0 + 0) * D_ + dd] =
                make_float4(lo2(c00), hi2(c00), lo2(c01), hi2(c01));
        if (u0 + 1 < U_)
            *(float4*)&pa[(u0 + 1) * D_ + dd] =
                make_float4(lo2(c10), hi2(c10), lo2(c11), hi2(c11));
        if (u0 + 2 < U_)
            *(float4*)&pa[(u0 + 2) * D_ + dd] =
                make_float4(lo2(c20), hi2(c20), lo2(c21), hi2(c21));
    }
}

// ---------------------------------------------------------------------------
// Kernel 6: combine partials. grid = (U_, B*H), 64 threads.
// ---------------------------------------------------------------------------
__global__ void __launch_bounds__(64) kernel_combine(float* __restrict__ out) {
    __shared__ float sw[NSPLIT];
    __shared__ float red[64];
    int u = blockIdx.x;
    int bh = blockIdx.y;
    int h = bh & 7, b = bh >> 3;
    int t = threadIdx.x;

    float m = g_pm[(bh * NSPLIT + t) * U_ + u];
    float s = g_ps[(bh * NSPLIT + t) * U_ + u];
    red[t] = m;
    __syncthreads();
    for (int st = 32; st; st >>= 1) {
        if (t < st) red[t] = fmaxf(red[t], red[t + st]);
        __syncthreads();
    }
    float M = red[0];
    __syncthreads();
    float e = __expf(m - M);
    red[t] = e * s;
    __syncthreads();
    for (int st = 32; st; st >>= 1) {
        if (t < st) red[t] += red[t + st];
        __syncthreads();
    }
    float inv = 1.0f / red[0];
    sw[t] = e * inv;
    __syncthreads();

    float acc = 0.0f;
    const float* pa = g_pacc + (size_t)bh * NSPLIT * U_ * D_ + u * D_ + t;
#pragma unroll 8
    for (int sp = 0; sp < NSPLIT; sp++)
        acc += pa[(size_t)sp * U_ * D_] * sw[sp];
    int lsel = g_Mtop[bh * U_ + u];
    out[((b * L_ + lsel) * H_ + h) * D_ + t] = acc;
}

// ---------------------------------------------------------------------------
// Launch: main = bucket -> M3 -> topk -> attn -> combine.
// Side s2 = mean -> fill, forked AFTER bucket (bucket zeroes vmean),
// joined before combine. M3 is submission #4 (ncu capture slot).
// ---------------------------------------------------------------------------
extern "C" void kernel_launch(void* const* d_in, const int* in_sizes, int n_in,
                              void* d_out, int out_size) {
    const float* Q = (const float*)d_in[0];
    const float* K = (const float*)d_in[1];
    const float* V = (const float*)d_in[2];
    const int* idx = (const int*)d_in[3];   // int32 (JAX x64 disabled)
    float* out = (float*)d_out;

    static cudaStream_t s2 = nullptr;
    static cudaEvent_t evFork = nullptr, evJoin = nullptr;
    if (s2 == nullptr) {
        cudaStreamCreateWithFlags(&s2, cudaStreamNonBlocking);
        cudaEventCreateWithFlags(&evFork, cudaEventDisableTiming);
        cudaEventCreateWithFlags(&evJoin, cudaEventDisableTiming);
        cudaFuncSetAttribute((const void*)kernel_M3,
                             cudaFuncAttributePreferredSharedMemoryCarveout, 0);
        cudaFuncSetAttribute((const void*)kernel_attn_part,
                             cudaFuncAttributeMaxDynamicSharedMemorySize, SMEM_BYTES);
    }

    // 1: bucket (also zeroes vmean) on the main stream
    kernel_bucket<<<16, 256>>>(idx);

    // Fork side stream AFTER bucket so mean_part sees zeroed vmean.
    cudaEventRecord(evFork, 0);
    cudaStreamWaitEvent(s2, evFork, 0);

    // 2,3: side chain on s2 (runs concurrently with M3)
    kernel_mean_part<<<B_ * H_ * 32, 256, 0, s2>>>(V);
    kernel_fill<<<(B_ * L_ * H_ * D_ / 4 + 255) / 256, 256, 0, s2>>>(out);

    // 4: chunked-gather M (ncu capture slot)
    kernel_M3<<<NCH * B_ * H_, 1024>>>(Q, K);
    // 5: topk
    kernel_topk<<<B_ * H_, 256>>>();
    // 6: attention
    kernel_attn_part<<<B_ * H_ * NSPLIT, 256, SMEM_BYTES>>>(Q, K, V);

    // Join side stream back, then combine (needs pacc + fill-complete).
    cudaEventRecord(evJoin, s2);
    cudaStreamWaitEvent(0, evJoin, 0);
    kernel_combine<<<dim3(U_, B_ * H_), 64>>>(out);
}

// round 12
// speedup vs baseline: 1.0680x; 1.0680x over previous
#include <cuda_runtime.h>
#include <math_constants.h>

// ProbAttention: B=4, L=4096, H=8, D=64, FACTOR=5
#define B_ 4
#define L_ 4096
#define H_ 8
#define D_ 64
#define SK_ 45
#define U_  45
#define NSPLIT 64
#define KC 64          // keys per split = L_/NSPLIT
#define PADK 68
#define NCH 4          // key chunks for chunked-gather M (1024 keys each)

// Scratch (device globals; no allocation allowed)
__device__ int   g_Mtop[B_ * H_ * U_];
__device__ float g_vmean[B_ * H_ * D_];
__device__ float g_pm[B_ * H_ * NSPLIT * U_];
__device__ float g_ps[B_ * H_ * NSPLIT * U_];
__device__ float g_pacc[B_ * H_ * NSPLIT * U_ * D_];   // 23.6 MB
__device__ int   g_blist[L_ * SK_];           // sample ids grouped by chunk
__device__ int   g_boff[L_ * (NCH + 1)];      // per-query chunk offsets
__device__ float g_pmax[NCH * B_ * H_ * L_];  // 2 MB
__device__ float g_psum[NCH * B_ * H_ * L_];  // 2 MB

typedef unsigned long long ull;
__device__ __forceinline__ float lo2(ull v) { return __uint_as_float((unsigned)v); }
__device__ __forceinline__ float hi2(ull v) { return __uint_as_float((unsigned)(v >> 32)); }
#define FMA2(acc, a, b) asm("fma.rn.f32x2 %0, %1, %2, %0;" : "+l"(acc) : "l"(a), "l"(b))
#define DUP2(out, x) asm("mov.b64 %0, {%1, %1};" : "=l"(out) : "r"(__float_as_uint(x)))

__device__ __forceinline__ unsigned smem_u32(const void* p) {
    return (unsigned)__cvta_generic_to_shared(p);
}

// ---------------------------------------------------------------------------
// Kernel A: bucket sample indices into NCH=4 key chunks (+ zero vmean).
// 16 blocks x 256 threads; one thread per query l.  (proven R11)
// ---------------------------------------------------------------------------
__global__ void __launch_bounds__(256) kernel_bucket(const int* __restrict__ idx) {
    int t = threadIdx.x;
    int l = blockIdx.x * 256 + t;
    int cnt[NCH + 1];
#pragma unroll
    for (int c = 0; c <= NCH; c++) cnt[c] = 0;
    const int* ip = idx + l * SK_;
    int samp[SK_];
#pragma unroll 5
    for (int s = 0; s < SK_; s++) { samp[s] = ip[s]; cnt[samp[s] >> 10]++; }
    int acc = 0;
#pragma unroll
    for (int c = 0; c < NCH; c++) {
        int v = cnt[c];
        g_boff[l * (NCH + 1) + c] = acc;
        cnt[c] = acc;
        acc += v;
    }
    g_boff[l * (NCH + 1) + NCH] = SK_;
#pragma unroll 5
    for (int s = 0; s < SK_; s++) {
        int v = samp[s];
        int c = v >> 10;
        g_blist[l * SK_ + cnt[c]++] = v;
    }
    if (blockIdx.x == 0)
        for (int i = t; i < B_ * H_ * D_; i += 256) g_vmean[i] = 0.0f;
}

// ---------------------------------------------------------------------------
// Kernel B: chunked-gather M, v2 (M4). grid = 512 blocks
// (qs = bid&3, bh = (bid>>2)&31, c = bid>>7), 1024 threads, 1 block/SM.
// Each block owns one (chunk,bh) and 1024 queries: the 256 KB K chunk goes
// L1-resident (proven by M3: DRAM 4%, L2 9%); execution uses kernel_M's
// proven shape — 8-lane row groups, 4 QUERIES per warp concurrently, so
// every SHFL/LDG instruction advances 4 independent dots.
// ---------------------------------------------------------------------------
__global__ void __launch_bounds__(1024, 1) kernel_M4(const float* __restrict__ Q,
                                                     const float* __restrict__ K) {
    int bid = blockIdx.x;
    int qs = bid & 3;
    int bh = (bid >> 2) & 31;
    int c  = bid >> 7;                    // 0..3
    int h = bh & 7, b = bh >> 3;
    int w = threadIdx.x >> 5;             // 0..31
    int lane = threadIdx.x & 31;
    int li = lane & 7;                    // lane within 8-lane row group
    int qg = lane >> 3;                   // query group 0..3

    float* pmax = g_pmax + ((c << 5) + bh) * L_;
    float* psum = g_psum + ((c << 5) + bh) * L_;

#pragma unroll 1
    for (int p = 0; p < 8; p++) {
        int l = qs * 1024 + p * 128 + w * 4 + qg;
        const float4* q4 = (const float4*)(Q + ((size_t)(b * L_ + l) * H_ + h) * D_);
        float4 qa = __ldcs(q4 + li * 2);
        float4 qb = __ldcs(q4 + li * 2 + 1);
        int st = __ldcs(&g_boff[l * (NCH + 1) + c]);
        int en = __ldcs(&g_boff[l * (NCH + 1) + c + 1]);
        int n = en - st;

        float mx = -CUDART_INF_F, sm = 0.0f;
        for (int i = 0; ; i++) {
            bool valid = (i < n);
            if (!__any_sync(0xffffffffu, valid)) break;
            int off = st + (valid ? i : 0);
            int kr = __ldcs(&g_blist[l * SK_ + off]);
            const float4* k4 = (const float4*)(K + ((size_t)(b * L_ + kr) * H_ + h) * D_);
            float4 ka = __ldg(k4 + li * 2);
            float4 kb = __ldg(k4 + li * 2 + 1);
            float d = qa.x * ka.x + qa.y * ka.y + qa.z * ka.z + qa.w * ka.w
                    + qb.x * kb.x + qb.y * kb.y + qb.z * kb.z + qb.w * kb.w;
            d += __shfl_xor_sync(0xffffffffu, d, 1);
            d += __shfl_xor_sync(0xffffffffu, d, 2);
            d += __shfl_xor_sync(0xffffffffu, d, 4);
            if (valid) { mx = fmaxf(mx, d); sm += d; }
        }
        if (li == 0) { pmax[l] = mx; psum[l] = sm; }
    }
}

// ---------------------------------------------------------------------------
// Kernel 2: top-U per (b,h): fold NCH chunk partials -> M keys, then
// two-level radix histogram + exact tail select.  (proven R11)
// ---------------------------------------------------------------------------
__device__ __forceinline__ unsigned f2key(float f) {
    unsigned u = __float_as_uint(f);
    return (u & 0x80000000u) ? ~u : (u | 0x80000000u);
}

__global__ void __launch_bounds__(256) kernel_topk() {
    __shared__ unsigned skeys[L_];
    __shared__ int hist[256];
    __shared__ unsigned candKey[1024];
    __shared__ int candIdx[1024];
    __shared__ int sT1, sN1, sT2;
    __shared__ int cSel, cCand;
    __shared__ unsigned rk[256];
    __shared__ int ri[256];

    int bh = blockIdx.x;
    int t = threadIdx.x;
    for (int i = t; i < L_; i += 256) {
        float mx = -CUDART_INF_F, sm = 0.0f;
#pragma unroll
        for (int c = 0; c < NCH; c++) {
            mx = fmaxf(mx, g_pmax[((c << 5) + bh) * L_ + i]);
            sm += g_psum[((c << 5) + bh) * L_ + i];
        }
        skeys[i] = f2key(mx - sm * (1.0f / (float)L_));
    }
    hist[t] = 0;
    __syncthreads();

    for (int i = t; i < L_; i += 256) atomicAdd(&hist[skeys[i] >> 24], 1);
    __syncthreads();
    if (t == 0) {
        int acc = 0;
        for (int bin = 255; bin >= 0; bin--) {
            if (acc + hist[bin] >= U_) { sT1 = bin; sN1 = acc; break; }
            acc += hist[bin];
        }
    }
    __syncthreads();
    int T1 = sT1, n1 = sN1;
    hist[t] = 0;
    __syncthreads();

    for (int i = t; i < L_; i += 256)
        if ((int)(skeys[i] >> 24) == T1) atomicAdd(&hist[(skeys[i] >> 16) & 255], 1);
    __syncthreads();
    if (t == 0) {
        int acc = n1;
        for (int bin = 255; bin >= 0; bin--) {
            if (acc + hist[bin] >= U_) { sT2 = bin; break; }
            acc += hist[bin];
        }
        cSel = 0; cCand = 0;
    }
    __syncthreads();
    unsigned TH16 = ((unsigned)T1 << 8) | (unsigned)sT2;

    for (int i = t; i < L_; i += 256) {
        unsigned k16 = skeys[i] >> 16;
        if (k16 > TH16) {
            int pos = atomicAdd(&cSel, 1);
            g_Mtop[bh * U_ + pos] = i;
        } else if (k16 == TH16) {
            int pos = atomicAdd(&cCand, 1);
            if (pos < 1024) { candKey[pos] = skeys[i]; candIdx[pos] = i; }
        }
    }
    __syncthreads();
    int ndef = cSel;
    int need = U_ - ndef;
    int nc = (cCand < 1024) ? cCand : 1024;

    for (int it = 0; it < need; it++) {
        unsigned best = 0; int bi = -1;
        for (int jj = t; jj < nc; jj += 256) {
            unsigned v = candKey[jj];
            if (v > best) { best = v; bi = jj; }
        }
        rk[t] = best; ri[t] = bi;
        __syncthreads();
        for (int s = 128; s; s >>= 1) {
            if (t < s && rk[t + s] > rk[t]) { rk[t] = rk[t + s]; ri[t] = ri[t + s]; }
            __syncthreads();
        }
        if (t == 0) {
            g_Mtop[bh * U_ + ndef + it] = candIdx[ri[0]];
            candKey[ri[0]] = 0;
        }
        __syncthreads();
    }
}

// ---------------------------------------------------------------------------
// Kernel 3: V mean partial sums (vmean zeroed by kernel_bucket)
// ---------------------------------------------------------------------------
__global__ void __launch_bounds__(256) kernel_mean_part(const float* __restrict__ V) {
    int blk = blockIdx.x;              // 1024 blocks
    int seg = blk & 31;
    int bh = blk >> 5;
    int h = bh & (H_ - 1);
    int b = bh >> 3;
    int t = threadIdx.x;
    int d4 = t & 15;
    int sub = t >> 4;
    int l0 = seg * 128;
    const float4* V4 = (const float4*)V;
    float ax = 0.f, ay = 0.f, az = 0.f, aw = 0.f;
#pragma unroll
    for (int i = 0; i < 8; i++) {
        int l = l0 + sub + i * 16;
        float4 v = V4[((size_t)(b * L_ + l) * H_ + h) * 16 + d4];
        ax += v.x; ay += v.y; az += v.z; aw += v.w;
    }
    __shared__ float4 s[16][16];
    s[sub][d4] = make_float4(ax, ay, az, aw);
    __syncthreads();
    if (t < 16) {
        float tx = 0.f, ty = 0.f, tz = 0.f, tw = 0.f;
#pragma unroll
        for (int jj = 0; jj < 16; jj++) {
            float4 v = s[jj][t];
            tx += v.x; ty += v.y; tz += v.z; tw += v.w;
        }
        atomicAdd(&g_vmean[bh * D_ + t * 4 + 0], tx);
        atomicAdd(&g_vmean[bh * D_ + t * 4 + 1], ty);
        atomicAdd(&g_vmean[bh * D_ + t * 4 + 2], tz);
        atomicAdd(&g_vmean[bh * D_ + t * 4 + 3], tw);
    }
}

// ---------------------------------------------------------------------------
// Kernel 4: fill out with V-mean broadcast (float4 stores)
// ---------------------------------------------------------------------------
__global__ void kernel_fill(float* __restrict__ out) {
    unsigned i = blockIdx.x * blockDim.x + threadIdx.x;  // float4 index
    int d4 = i & 15;
    int h = (i >> 4) & 7;
    int b = i >> 19;
    const float4* vm4 = (const float4*)g_vmean;
    float4 v = vm4[(b * H_ + h) * 16 + d4];
    const float inv = 1.0f / (float)L_;
    ((float4*)out)[i] = make_float4(v.x * inv, v.y * inv, v.z * inv, v.w * inv);
}

// ---------------------------------------------------------------------------
// Kernel 5: split-KV attention (round-6 proven version: NSPLIT=64, KC=64).
// cp.async V prefetch; register softmax; f32x2 FMAs.  (measured 58.1us)
// ---------------------------------------------------------------------------
#define OFF_V   (64 * PADK)
#define OFF_QE  (OFF_V + 64 * PADK)
#define OFF_MT  (OFF_QE + 48 * 64)
#define SMEM_FLOATS (OFF_MT + 64)
#define SMEM_BYTES  (SMEM_FLOATS * 4)

__global__ void __launch_bounds__(256) kernel_attn_part(
        const float* __restrict__ Q,
        const float* __restrict__ K,
        const float* __restrict__ V) {
    extern __shared__ float smem[];
    float* sKT = smem;                  // [64][PADK]  K transposed [d][k]
    float* sV  = smem + OFF_V;          // [64][PADK]  V natural   [k][d]
    float* sQE = smem + OFF_QE;         // [48][64]    Q rows, then E rows
    int*   sMt = (int*)(smem + OFF_MT);

    int bh = blockIdx.x >> 6;
    int sp = blockIdx.x & 63;
    int h = bh & 7, b = bh >> 3;
    int k0 = sp * KC;
    int t = threadIdx.x;

    {
        const char* vbase = (const char*)(V + ((size_t)(b * L_ + k0) * H_ + h) * D_);
#pragma unroll
        for (int i = 0; i < 4; i++) {
            int e = t + i * 256;
            int row = e >> 4, c = e & 15;
            unsigned dst = smem_u32(sV + row * PADK + c * 4);
            const char* src = vbase + (size_t)row * (H_ * D_ * 4) + c * 16;
            asm volatile("cp.async.cg.shared.global [%0], [%1], 16;"
                         :: "r"(dst), "l"(src));
        }
        asm volatile("cp.async.commit_group;");
    }

    if (t < U_) sMt[t] = g_Mtop[bh * U_ + t];
    __syncthreads();

#pragma unroll
    for (int i = 0; i < 3; i++) {
        int e = t + i * 256;
        int u = e >> 4, c = e & 15;
        float4 q = make_float4(0.f, 0.f, 0.f, 0.f);
        if (u < U_)
            q = *(const float4*)(Q + ((b * L_ + sMt[u]) * H_ + h) * D_ + c * 4);
        *(float4*)(sQE + u * 64 + c * 4) = q;
    }
#pragma unroll
    for (int i = 0; i < 16; i++) {
        int e = t + i * 256;
        int k = e >> 6, d = e & 63;
        sKT[d * PADK + k] = K[((b * L_ + k0 + k) * H_ + h) * D_ + d];
    }
    __syncthreads();

    int kt = t & 15, ut = t >> 4;
    int kk = kt * 4, u0 = ut * 3;

    ull a00 = 0, a01 = 0, a10 = 0, a11 = 0, a20 = 0, a21 = 0;
    {
        const float* q0p = sQE + (u0 + 0) * 64;
        const float* q1p = sQE + (u0 + 1) * 64;
        const float* q2p = sQE + (u0 + 2) * 64;
#pragma unroll 8
        for (int d = 0; d < 64; d++) {
            ulonglong2 kv = *(const ulonglong2*)&sKT[d * PADK + kk];
            ull q0, q1, q2;
            DUP2(q0, q0p[d]); DUP2(q1, q1p[d]); DUP2(q2, q2p[d]);
            FMA2(a00, q0, kv.x); FMA2(a01, q0, kv.y);
            FMA2(a10, q1, kv.x); FMA2(a11, q1, kv.y);
            FMA2(a20, q2, kv.x); FMA2(a21, q2, kv.y);
        }
    }

    float ev[3][4];
    {
        const float sc = 0.125f;
        ull ra[3][2] = {{a00, a01}, {a10, a11}, {a20, a21}};
#pragma unroll
        for (int jj = 0; jj < 3; jj++) {
            float s0 = lo2(ra[jj][0]) * sc, s1 = hi2(ra[jj][0]) * sc;
            float s2 = lo2(ra[jj][1]) * sc, s3 = hi2(ra[jj][1]) * sc;
            float mm = fmaxf(fmaxf(s0, s1), fmaxf(s2, s3));
            mm = fmaxf(mm, __shfl_xor_sync(0xffffffffu, mm, 1));
            mm = fmaxf(mm, __shfl_xor_sync(0xffffffffu, mm, 2));
            mm = fmaxf(mm, __shfl_xor_sync(0xffffffffu, mm, 4));
            mm = fmaxf(mm, __shfl_xor_sync(0xffffffffu, mm, 8));
            float e0 = __expf(s0 - mm), e1 = __expf(s1 - mm);
            float e2 = __expf(s2 - mm), e3 = __expf(s3 - mm);
            float ss = (e0 + e1) + (e2 + e3);
            ss += __shfl_xor_sync(0xffffffffu, ss, 1);
            ss += __shfl_xor_sync(0xffffffffu, ss, 2);
            ss += __shfl_xor_sync(0xffffffffu, ss, 4);
            ss += __shfl_xor_sync(0xffffffffu, ss, 8);
            ev[jj][0] = e0; ev[jj][1] = e1; ev[jj][2] = e2; ev[jj][3] = e3;
            int u = u0 + jj;
            if (kt == 0 && u < U_) {
                g_pm[(bh * NSPLIT + sp) * U_ + u] = mm;
                g_ps[(bh * NSPLIT + sp) * U_ + u] = ss;
            }
        }
    }
    __syncthreads();

#pragma unroll
    for (int jj = 0; jj < 3; jj++)
        *(float4*)(sQE + (u0 + jj) * 64 + kk) =
            make_float4(ev[jj][0], ev[jj][1], ev[jj][2], ev[jj][3]);

    asm volatile("cp.async.wait_group 0;");
    __syncthreads();

    {
        int dd = kk;
        ull c00 = 0, c01 = 0, c10 = 0, c11 = 0, c20 = 0, c21 = 0;
        const float* e0p = sQE + (u0 + 0) * 64;
        const float* e1p = sQE + (u0 + 1) * 64;
        const float* e2p = sQE + (u0 + 2) * 64;
#pragma unroll 8
        for (int k = 0; k < 64; k++) {
            ulonglong2 vv = *(const ulonglong2*)&sV[k * PADK + dd];
            ull e0, e1, e2;
            DUP2(e0, e0p[k]); DUP2(e1, e1p[k]); DUP2(e2, e2p[k]);
            FMA2(c00, e0, vv.x); FMA2(c01, e0, vv.y);
            FMA2(c10, e1, vv.x); FMA2(c11, e1, vv.y);
            FMA2(c20, e2, vv.x); FMA2(c21, e2, vv.y);
        }
        float* pa = g_pacc + (size_t)(bh * NSPLIT + sp) * U_ * D_;
        if (u0 + 0 < U_)
            *(float4*)&pa[(u0 + 0) * D_ + dd] =
                make_float4(lo2(c00), hi2(c00), lo2(c01), hi2(c01));
        if (u0 + 1 < U_)
            *(float4*)&pa[(u0 + 1) * D_ + dd] =
                make_float4(lo2(c10), hi2(c10), lo2(c11), hi2(c11));
        if (u0 + 2 < U_)
            *(float4*)&pa[(u0 + 2) * D_ + dd] =
                make_float4(lo2(c20), hi2(c20), lo2(c21), hi2(c21));
    }
}

// ---------------------------------------------------------------------------
// Kernel 6: combine partials. grid = (U_, B*H), 64 threads.
// ---------------------------------------------------------------------------
__global__ void __launch_bounds__(64) kernel_combine(float* __restrict__ out) {
    __shared__ float sw[NSPLIT];
    __shared__ float red[64];
    int u = blockIdx.x;
    int bh = blockIdx.y;
    int h = bh & 7, b = bh >> 3;
    int t = threadIdx.x;

    float m = g_pm[(bh * NSPLIT + t) * U_ + u];
    float s = g_ps[(bh * NSPLIT + t) * U_ + u];
    red[t] = m;
    __syncthreads();
    for (int st = 32; st; st >>= 1) {
        if (t < st) red[t] = fmaxf(red[t], red[t + st]);
        __syncthreads();
    }
    float M = red[0];
    __syncthreads();
    float e = __expf(m - M);
    red[t] = e * s;
    __syncthreads();
    for (int st = 32; st; st >>= 1) {
        if (t < st) red[t] += red[t + st];
        __syncthreads();
    }
    float inv = 1.0f / red[0];
    sw[t] = e * inv;
    __syncthreads();

    float acc = 0.0f;
    const float* pa = g_pacc + (size_t)bh * NSPLIT * U_ * D_ + u * D_ + t;
#pragma unroll 8
    for (int sp = 0; sp < NSPLIT; sp++)
        acc += pa[(size_t)sp * U_ * D_] * sw[sp];
    int lsel = g_Mtop[bh * U_ + u];
    out[((b * L_ + lsel) * H_ + h) * D_ + t] = acc;
}

// ---------------------------------------------------------------------------
// Launch: main = bucket -> M4 -> topk -> attn -> combine.
// Side s2 = mean -> fill, forked AFTER bucket (bucket zeroes vmean),
// joined before combine. M4 is submission #4 (ncu capture slot).
// ---------------------------------------------------------------------------
extern "C" void kernel_launch(void* const* d_in, const int* in_sizes, int n_in,
                              void* d_out, int out_size) {
    const float* Q = (const float*)d_in[0];
    const float* K = (const float*)d_in[1];
    const float* V = (const float*)d_in[2];
    const int* idx = (const int*)d_in[3];   // int32 (JAX x64 disabled)
    float* out = (float*)d_out;

    static cudaStream_t s2 = nullptr;
    static cudaEvent_t evFork = nullptr, evJoin = nullptr;
    if (s2 == nullptr) {
        cudaStreamCreateWithFlags(&s2, cudaStreamNonBlocking);
        cudaEventCreateWithFlags(&evFork, cudaEventDisableTiming);
        cudaEventCreateWithFlags(&evJoin, cudaEventDisableTiming);
        cudaFuncSetAttribute((const void*)kernel_M4,
                             cudaFuncAttributePreferredSharedMemoryCarveout, 0);
        cudaFuncSetAttribute((const void*)kernel_attn_part,
                             cudaFuncAttributeMaxDynamicSharedMemorySize, SMEM_BYTES);
    }

    // 1: bucket (also zeroes vmean) on the main stream
    kernel_bucket<<<16, 256>>>(idx);

    // Fork side stream AFTER bucket so mean_part sees zeroed vmean.
    cudaEventRecord(evFork, 0);
    cudaStreamWaitEvent(s2, evFork, 0);

    // 2,3: side chain on s2 (runs concurrently with M4)
    kernel_mean_part<<<B_ * H_ * 32, 256, 0, s2>>>(V);
    kernel_fill<<<(B_ * L_ * H_ * D_ / 4 + 255) / 256, 256, 0, s2>>>(out);

    // 4: chunked-gather M v2 (ncu capture slot)
    kernel_M4<<<NCH * B_ * H_ * 4, 1024>>>(Q, K);
    // 5: topk (folds chunk partials)
    kernel_topk<<<B_ * H_, 256>>>();
    // 6: attention
    kernel_attn_part<<<B_ * H_ * NSPLIT, 256, SMEM_BYTES>>>(Q, K, V);

    // Join side stream back, then combine (needs pacc + fill-complete).
    cudaEventRecord(evJoin, s2);
    cudaStreamWaitEvent(0, evJoin, 0);
    kernel_combine<<<dim3(U_, B_ * H_), 64>>>(out);
}

// round 13
// speedup vs baseline: 1.3421x; 1.2566x over previous
#include <cuda_runtime.h>
#include <math_constants.h>

// ProbAttention: B=4, L=4096, H=8, D=64, FACTOR=5
#define B_ 4
#define L_ 4096
#define H_ 8
#define D_ 64
#define SK_ 45
#define U_  45
#define NSPLIT 64
#define KC 64          // keys per split = L_/NSPLIT
#define PADK 68
#define NQ 4           // pipeline quarters over bh
#define BH_PER_Q (B_ * H_ / NQ)   // 8

// Scratch (device globals; no allocation allowed)
__device__ float g_M[B_ * H_ * L_];
__device__ int   g_Mtop[B_ * H_ * U_];
__device__ float g_vmean[B_ * H_ * D_];
__device__ float g_pm[B_ * H_ * NSPLIT * U_];
__device__ float g_ps[B_ * H_ * NSPLIT * U_];
__device__ float g_pacc[B_ * H_ * NSPLIT * U_ * D_];   // 23.6 MB

typedef unsigned long long ull;
__device__ __forceinline__ float lo2(ull v) { return __uint_as_float((unsigned)v); }
__device__ __forceinline__ float hi2(ull v) { return __uint_as_float((unsigned)(v >> 32)); }
#define FMA2(acc, a, b) asm("fma.rn.f32x2 %0, %1, %2, %0;" : "+l"(acc) : "l"(a), "l"(b))
#define DUP2(out, x) asm("mov.b64 %0, {%1, %1};" : "=l"(out) : "r"(__float_as_uint(x)))

__device__ __forceinline__ unsigned smem_u32(const void* p) {
    return (unsigned)__cvta_generic_to_shared(p);
}

// ---------------------------------------------------------------------------
// Kernel 1: M scores, quarter version. 4096 blocks cover 8 bh (w_base..).
// Body identical to the proven gather kernel (measured at the LTS cap).
// ---------------------------------------------------------------------------
__global__ void __launch_bounds__(256) kernel_M(const float* __restrict__ Q,
                                                const float* __restrict__ K,
                                                const int* __restrict__ idx,
                                                int w_base) {
    int j = (blockIdx.x * 111) & 4095;       // bijective remap within quarter
    int w = w_base + j * 8 + (threadIdx.x >> 5);
    int lane = threadIdx.x & 31;
    int li = lane & 7;
    int g  = lane >> 3;
    int l = w & (L_ - 1);
    int h = (w >> 12) & (H_ - 1);
    int b = w >> 15;

    const float4* q4 = (const float4*)(Q + ((b * L_ + l) * H_ + h) * D_);
    float4 qa = q4[li * 2];
    float4 qb = q4[li * 2 + 1];

    const int* ip = idx + l * SK_;
    float mx = -CUDART_INF_F;
    float sm = 0.0f;
#pragma unroll
    for (int sg = 0; sg < 12; sg++) {
        int s = sg * 4 + g;
        bool valid = (s < SK_);
        int kr = ip[valid ? s : 0];
        const float4* k4 = (const float4*)(K + ((b * L_ + kr) * H_ + h) * D_);
        float4 ka = k4[li * 2];
        float4 kb = k4[li * 2 + 1];
        float d = qa.x * ka.x + qa.y * ka.y + qa.z * ka.z + qa.w * ka.w
                + qb.x * kb.x + qb.y * kb.y + qb.z * kb.z + qb.w * kb.w;
        d += __shfl_xor_sync(0xffffffffu, d, 4);
        d += __shfl_xor_sync(0xffffffffu, d, 2);
        d += __shfl_xor_sync(0xffffffffu, d, 1);
        if (valid) { mx = fmaxf(mx, d); sm += d; }
    }
    mx = fmaxf(mx, __shfl_xor_sync(0xffffffffu, mx, 8));
    mx = fmaxf(mx, __shfl_xor_sync(0xffffffffu, mx, 16));
    sm += __shfl_xor_sync(0xffffffffu, sm, 8);
    sm += __shfl_xor_sync(0xffffffffu, sm, 16);
    if (lane == 0) g_M[w] = mx - sm * (1.0f / (float)L_);
}

// ---------------------------------------------------------------------------
// Kernel 2: top-U per (b,h), quarter version (8 blocks per launch).
// ---------------------------------------------------------------------------
__device__ __forceinline__ unsigned f2key(float f) {
    unsigned u = __float_as_uint(f);
    return (u & 0x80000000u) ? ~u : (u | 0x80000000u);
}

__global__ void __launch_bounds__(256) kernel_topk(int bh_base) {
    __shared__ unsigned skeys[L_];
    __shared__ int hist[256];
    __shared__ unsigned candKey[1024];
    __shared__ int candIdx[1024];
    __shared__ int sT1, sN1, sT2;
    __shared__ int cSel, cCand;
    __shared__ unsigned rk[256];
    __shared__ int ri[256];

    int bh = bh_base + blockIdx.x;
    int t = threadIdx.x;
    const float* m = g_M + bh * L_;
    for (int i = t; i < L_; i += 256) skeys[i] = f2key(m[i]);
    hist[t] = 0;
    __syncthreads();

    for (int i = t; i < L_; i += 256) atomicAdd(&hist[skeys[i] >> 24], 1);
    __syncthreads();
    if (t == 0) {
        int acc = 0;
        for (int bin = 255; bin >= 0; bin--) {
            if (acc + hist[bin] >= U_) { sT1 = bin; sN1 = acc; break; }
            acc += hist[bin];
        }
    }
    __syncthreads();
    int T1 = sT1, n1 = sN1;
    hist[t] = 0;
    __syncthreads();

    for (int i = t; i < L_; i += 256)
        if ((int)(skeys[i] >> 24) == T1) atomicAdd(&hist[(skeys[i] >> 16) & 255], 1);
    __syncthreads();
    if (t == 0) {
        int acc = n1;
        for (int bin = 255; bin >= 0; bin--) {
            if (acc + hist[bin] >= U_) { sT2 = bin; break; }
            acc += hist[bin];
        }
        cSel = 0; cCand = 0;
    }
    __syncthreads();
    unsigned TH16 = ((unsigned)T1 << 8) | (unsigned)sT2;

    for (int i = t; i < L_; i += 256) {
        unsigned k16 = skeys[i] >> 16;
        if (k16 > TH16) {
            int pos = atomicAdd(&cSel, 1);
            g_Mtop[bh * U_ + pos] = i;
        } else if (k16 == TH16) {
            int pos = atomicAdd(&cCand, 1);
            if (pos < 1024) { candKey[pos] = skeys[i]; candIdx[pos] = i; }
        }
    }
    __syncthreads();
    int ndef = cSel;
    int need = U_ - ndef;
    int nc = (cCand < 1024) ? cCand : 1024;

    for (int it = 0; it < need; it++) {
        unsigned best = 0; int bi = -1;
        for (int jj = t; jj < nc; jj += 256) {
            unsigned v = candKey[jj];
            if (v > best) { best = v; bi = jj; }
        }
        rk[t] = best; ri[t] = bi;
        __syncthreads();
        for (int s = 128; s; s >>= 1) {
            if (t < s && rk[t + s] > rk[t]) { rk[t] = rk[t + s]; ri[t] = ri[t + s]; }
            __syncthreads();
        }
        if (t == 0) {
            g_Mtop[bh * U_ + ndef + it] = candIdx[ri[0]];
            candKey[ri[0]] = 0;
        }
        __syncthreads();
    }
}

// ---------------------------------------------------------------------------
// Kernel 3: V mean (zero + float4 partial sums)
// ---------------------------------------------------------------------------
__global__ void kernel_zero_mean() {
    int i = blockIdx.x * blockDim.x + threadIdx.x;
    if (i < B_ * H_ * D_) g_vmean[i] = 0.0f;
}

__global__ void __launch_bounds__(256) kernel_mean_part(const float* __restrict__ V) {
    int blk = blockIdx.x;              // 1024 blocks
    int seg = blk & 31;
    int bh = blk >> 5;
    int h = bh & (H_ - 1);
    int b = bh >> 3;
    int t = threadIdx.x;
    int d4 = t & 15;
    int sub = t >> 4;
    int l0 = seg * 128;
    const float4* V4 = (const float4*)V;
    float ax = 0.f, ay = 0.f, az = 0.f, aw = 0.f;
#pragma unroll
    for (int i = 0; i < 8; i++) {
        int l = l0 + sub + i * 16;
        float4 v = V4[((size_t)(b * L_ + l) * H_ + h) * 16 + d4];
        ax += v.x; ay += v.y; az += v.z; aw += v.w;
    }
    __shared__ float4 s[16][16];
    s[sub][d4] = make_float4(ax, ay, az, aw);
    __syncthreads();
    if (t < 16) {
        float tx = 0.f, ty = 0.f, tz = 0.f, tw = 0.f;
#pragma unroll
        for (int jj = 0; jj < 16; jj++) {
            float4 v = s[jj][t];
            tx += v.x; ty += v.y; tz += v.z; tw += v.w;
        }
        atomicAdd(&g_vmean[bh * D_ + t * 4 + 0], tx);
        atomicAdd(&g_vmean[bh * D_ + t * 4 + 1], ty);
        atomicAdd(&g_vmean[bh * D_ + t * 4 + 2], tz);
        atomicAdd(&g_vmean[bh * D_ + t * 4 + 3], tw);
    }
}

// ---------------------------------------------------------------------------
// Kernel 4: fill out with V-mean broadcast (float4 stores)
// ---------------------------------------------------------------------------
__global__ void kernel_fill(float* __restrict__ out) {
    unsigned i = blockIdx.x * blockDim.x + threadIdx.x;  // float4 index
    int d4 = i & 15;
    int h = (i >> 4) & 7;
    int b = i >> 19;
    const float4* vm4 = (const float4*)g_vmean;
    float4 v = vm4[(b * H_ + h) * 16 + d4];
    const float inv = 1.0f / (float)L_;
    ((float4*)out)[i] = make_float4(v.x * inv, v.y * inv, v.z * inv, v.w * inv);
}

// ---------------------------------------------------------------------------
// Kernel 5: split-KV attention, quarter version (512 blocks per launch).
// Body identical to the proven round-6 kernel (58.1us full-size).
// ---------------------------------------------------------------------------
#define OFF_V   (64 * PADK)
#define OFF_QE  (OFF_V + 64 * PADK)
#define OFF_MT  (OFF_QE + 48 * 64)
#define SMEM_FLOATS (OFF_MT + 64)
#define SMEM_BYTES  (SMEM_FLOATS * 4)

__global__ void __launch_bounds__(256) kernel_attn_part(
        const float* __restrict__ Q,
        const float* __restrict__ K,
        const float* __restrict__ V,
        int bh_base) {
    extern __shared__ float smem[];
    float* sKT = smem;                  // [64][PADK]  K transposed [d][k]
    float* sV  = smem + OFF_V;          // [64][PADK]  V natural   [k][d]
    float* sQE = smem + OFF_QE;         // [48][64]    Q rows, then E rows
    int*   sMt = (int*)(smem + OFF_MT);

    int bh = bh_base + (blockIdx.x >> 6);
    int sp = blockIdx.x & 63;
    int h = bh & 7, b = bh >> 3;
    int k0 = sp * KC;
    int t = threadIdx.x;

    {
        const char* vbase = (const char*)(V + ((size_t)(b * L_ + k0) * H_ + h) * D_);
#pragma unroll
        for (int i = 0; i < 4; i++) {
            int e = t + i * 256;
            int row = e >> 4, c = e & 15;
            unsigned dst = smem_u32(sV + row * PADK + c * 4);
            const char* src = vbase + (size_t)row * (H_ * D_ * 4) + c * 16;
            asm volatile("cp.async.cg.shared.global [%0], [%1], 16;"
                         :: "r"(dst), "l"(src));
        }
        asm volatile("cp.async.commit_group;");
    }

    if (t < U_) sMt[t] = g_Mtop[bh * U_ + t];
    __syncthreads();

#pragma unroll
    for (int i = 0; i < 3; i++) {
        int e = t + i * 256;
        int u = e >> 4, c = e & 15;
        float4 q = make_float4(0.f, 0.f, 0.f, 0.f);
        if (u < U_)
            q = *(const float4*)(Q + ((b * L_ + sMt[u]) * H_ + h) * D_ + c * 4);
        *(float4*)(sQE + u * 64 + c * 4) = q;
    }
#pragma unroll
    for (int i = 0; i < 16; i++) {
        int e = t + i * 256;
        int k = e >> 6, d = e & 63;
        sKT[d * PADK + k] = K[((b * L_ + k0 + k) * H_ + h) * D_ + d];
    }
    __syncthreads();

    int kt = t & 15, ut = t >> 4;
    int kk = kt * 4, u0 = ut * 3;

    ull a00 = 0, a01 = 0, a10 = 0, a11 = 0, a20 = 0, a21 = 0;
    {
        const float* q0p = sQE + (u0 + 0) * 64;
        const float* q1p = sQE + (u0 + 1) * 64;
        const float* q2p = sQE + (u0 + 2) * 64;
#pragma unroll 8
        for (int d = 0; d < 64; d++) {
            ulonglong2 kv = *(const ulonglong2*)&sKT[d * PADK + kk];
            ull q0, q1, q2;
            DUP2(q0, q0p[d]); DUP2(q1, q1p[d]); DUP2(q2, q2p[d]);
            FMA2(a00, q0, kv.x); FMA2(a01, q0, kv.y);
            FMA2(a10, q1, kv.x); FMA2(a11, q1, kv.y);
            FMA2(a20, q2, kv.x); FMA2(a21, q2, kv.y);
        }
    }

    float ev[3][4];
    {
        const float sc = 0.125f;
        ull ra[3][2] = {{a00, a01}, {a10, a11}, {a20, a21}};
#pragma unroll
        for (int jj = 0; jj < 3; jj++) {
            float s0 = lo2(ra[jj][0]) * sc, s1 = hi2(ra[jj][0]) * sc;
            float s2 = lo2(ra[jj][1]) * sc, s3 = hi2(ra[jj][1]) * sc;
            float mm = fmaxf(fmaxf(s0, s1), fmaxf(s2, s3));
            mm = fmaxf(mm, __shfl_xor_sync(0xffffffffu, mm, 1));
            mm = fmaxf(mm, __shfl_xor_sync(0xffffffffu, mm, 2));
            mm = fmaxf(mm, __shfl_xor_sync(0xffffffffu, mm, 4));
            mm = fmaxf(mm, __shfl_xor_sync(0xffffffffu, mm, 8));
            float e0 = __expf(s0 - mm), e1 = __expf(s1 - mm);
            float e2 = __expf(s2 - mm), e3 = __expf(s3 - mm);
            float ss = (e0 + e1) + (e2 + e3);
            ss += __shfl_xor_sync(0xffffffffu, ss, 1);
            ss += __shfl_xor_sync(0xffffffffu, ss, 2);
            ss += __shfl_xor_sync(0xffffffffu, ss, 4);
            ss += __shfl_xor_sync(0xffffffffu, ss, 8);
            ev[jj][0] = e0; ev[jj][1] = e1; ev[jj][2] = e2; ev[jj][3] = e3;
            int u = u0 + jj;
            if (kt == 0 && u < U_) {
                g_pm[(bh * NSPLIT + sp) * U_ + u] = mm;
                g_ps[(bh * NSPLIT + sp) * U_ + u] = ss;
            }
        }
    }
    __syncthreads();

#pragma unroll
    for (int jj = 0; jj < 3; jj++)
        *(float4*)(sQE + (u0 + jj) * 64 + kk) =
            make_float4(ev[jj][0], ev[jj][1], ev[jj][2], ev[jj][3]);

    asm volatile("cp.async.wait_group 0;");
    __syncthreads();

    {
        int dd = kk;
        ull c00 = 0, c01 = 0, c10 = 0, c11 = 0, c20 = 0, c21 = 0;
        const float* e0p = sQE + (u0 + 0) * 64;
        const float* e1p = sQE + (u0 + 1) * 64;
        const float* e2p = sQE + (u0 + 2) * 64;
#pragma unroll 8
        for (int k = 0; k < 64; k++) {
            ulonglong2 vv = *(const ulonglong2*)&sV[k * PADK + dd];
            ull e0, e1, e2;
            DUP2(e0, e0p[k]); DUP2(e1, e1p[k]); DUP2(e2, e2p[k]);
            FMA2(c00, e0, vv.x); FMA2(c01, e0, vv.y);
            FMA2(c10, e1, vv.x); FMA2(c11, e1, vv.y);
            FMA2(c20, e2, vv.x); FMA2(c21, e2, vv.y);
        }
        float* pa = g_pacc + (size_t)(bh * NSPLIT + sp) * U_ * D_;
        if (u0 + 0 < U_)
            *(float4*)&pa[(u0 + 0) * D_ + dd] =
                make_float4(lo2(c00), hi2(c00), lo2(c01), hi2(c01));
        if (u0 + 1 < U_)
            *(float4*)&pa[(u0 + 1) * D_ + dd] =
                make_float4(lo2(c10), hi2(c10), lo2(c11), hi2(c11));
        if (u0 + 2 < U_)
            *(float4*)&pa[(u0 + 2) * D_ + dd] =
                make_float4(lo2(c20), hi2(c20), lo2(c21), hi2(c21));
    }
}

// ---------------------------------------------------------------------------
// Kernel 6: combine partials, quarter version. grid = (U_, 8), 64 threads.
// ---------------------------------------------------------------------------
__global__ void __launch_bounds__(64) kernel_combine(float* __restrict__ out,
                                                     int bh_base) {
    __shared__ float sw[NSPLIT];
    __shared__ float red[64];
    int u = blockIdx.x;
    int bh = bh_base + blockIdx.y;
    int h = bh & 7, b = bh >> 3;
    int t = threadIdx.x;

    float m = g_pm[(bh * NSPLIT + t) * U_ + u];
    float s = g_ps[(bh * NSPLIT + t) * U_ + u];
    red[t] = m;
    __syncthreads();
    for (int st = 32; st; st >>= 1) {
        if (t < st) red[t] = fmaxf(red[t], red[t + st]);
        __syncthreads();
    }
    float M = red[0];
    __syncthreads();
    float e = __expf(m - M);
    red[t] = e * s;
    __syncthreads();
    for (int st = 32; st; st >>= 1) {
        if (t < st) red[t] += red[t + st];
        __syncthreads();
    }
    float inv = 1.0f / red[0];
    sw[t] = e * inv;
    __syncthreads();

    float acc = 0.0f;
    const float* pa = g_pacc + (size_t)bh * NSPLIT * U_ * D_ + u * D_ + t;
#pragma unroll 8
    for (int sp = 0; sp < NSPLIT; sp++)
        acc += pa[(size_t)sp * U_ * D_] * sw[sp];
    int lsel = g_Mtop[bh * U_ + u];
    out[((b * L_ + lsel) * H_ + h) * D_ + t] = acc;
}

// ---------------------------------------------------------------------------
// Launch: bh-quartered pipeline.
//   main: M1 M2 M3 M4 then chain4 (topk4 attn4 combine4)
//   s2:   zero mean fill, then chain_q (q=1..3) gated on evM[q] — each
//         chain runs in the shadow of the next M quarter.
// combine needs fill (s2 order guarantees it for chains 1-3; main waits
// evFill before combine4). Main waits evJoin (end of s2) at the end.
// ---------------------------------------------------------------------------
extern "C" void kernel_launch(void* const* d_in, const int* in_sizes, int n_in,
                              void* d_out, int out_size) {
    const float* Q = (const float*)d_in[0];
    const float* K = (const float*)d_in[1];
    const float* V = (const float*)d_in[2];
    const int* idx = (const int*)d_in[3];   // int32 (JAX x64 disabled)
    float* out = (float*)d_out;

    static cudaStream_t s2 = nullptr;
    static cudaEvent_t evFork = nullptr, evM1, evM2, evM3, evFill, evJoin;
    if (s2 == nullptr) {
        cudaStreamCreateWithFlags(&s2, cudaStreamNonBlocking);
        cudaEventCreateWithFlags(&evFork, cudaEventDisableTiming);
        cudaEventCreateWithFlags(&evM1, cudaEventDisableTiming);
        cudaEventCreateWithFlags(&evM2, cudaEventDisableTiming);
        cudaEventCreateWithFlags(&evM3, cudaEventDisableTiming);
        cudaEventCreateWithFlags(&evFill, cudaEventDisableTiming);
        cudaEventCreateWithFlags(&evJoin, cudaEventDisableTiming);
        cudaFuncSetAttribute((const void*)kernel_M,
                             cudaFuncAttributePreferredSharedMemoryCarveout, 0);
        cudaFuncSetAttribute((const void*)kernel_attn_part,
                             cudaFuncAttributeMaxDynamicSharedMemorySize, SMEM_BYTES);
    }

    const int MBLK = (BH_PER_Q * L_) / 8;         // 4096 blocks per quarter
    const int WQ = BH_PER_Q * L_;                  // w stride per quarter

    // Fork s2 off the capturing stream.
    cudaEventRecord(evFork, 0);
    cudaStreamWaitEvent(s2, evFork, 0);

    // s2: independent mean/fill chain (positions 1-3)
    kernel_zero_mean<<<(B_ * H_ * D_ + 255) / 256, 256, 0, s2>>>();
    kernel_mean_part<<<B_ * H_ * 32, 256, 0, s2>>>(V);
    kernel_fill<<<(B_ * L_ * H_ * D_ / 4 + 255) / 256, 256, 0, s2>>>(out);
    cudaEventRecord(evFill, s2);

    // main: M quarters (position 4 = M1 -> ncu capture slot)
    kernel_M<<<MBLK, 256>>>(Q, K, idx, 0 * WQ);
    cudaEventRecord(evM1, 0);
    kernel_M<<<MBLK, 256>>>(Q, K, idx, 1 * WQ);
    cudaEventRecord(evM2, 0);
    kernel_M<<<MBLK, 256>>>(Q, K, idx, 2 * WQ);
    cudaEventRecord(evM3, 0);
    kernel_M<<<MBLK, 256>>>(Q, K, idx, 3 * WQ);

    // s2: quarter chains 1..3, each gated on its M quarter
    cudaStreamWaitEvent(s2, evM1, 0);
    kernel_topk<<<BH_PER_Q, 256, 0, s2>>>(0 * BH_PER_Q);
    kernel_attn_part<<<BH_PER_Q * NSPLIT, 256, SMEM_BYTES, s2>>>(Q, K, V, 0 * BH_PER_Q);
    kernel_combine<<<dim3(U_, BH_PER_Q), 64, 0, s2>>>(out, 0 * BH_PER_Q);

    cudaStreamWaitEvent(s2, evM2, 0);
    kernel_topk<<<BH_PER_Q, 256, 0, s2>>>(1 * BH_PER_Q);
    kernel_attn_part<<<BH_PER_Q * NSPLIT, 256, SMEM_BYTES, s2>>>(Q, K, V, 1 * BH_PER_Q);
    kernel_combine<<<dim3(U_, BH_PER_Q), 64, 0, s2>>>(out, 1 * BH_PER_Q);

    cudaStreamWaitEvent(s2, evM3, 0);
    kernel_topk<<<BH_PER_Q, 256, 0, s2>>>(2 * BH_PER_Q);
    kernel_attn_part<<<BH_PER_Q * NSPLIT, 256, SMEM_BYTES, s2>>>(Q, K, V, 2 * BH_PER_Q);
    kernel_combine<<<dim3(U_, BH_PER_Q), 64, 0, s2>>>(out, 2 * BH_PER_Q);

    // main: chain 4 (after M4; combine4 additionally needs fill)
    kernel_topk<<<BH_PER_Q, 256>>>(3 * BH_PER_Q);
    kernel_attn_part<<<BH_PER_Q * NSPLIT, 256, SMEM_BYTES>>>(Q, K, V, 3 * BH_PER_Q);
    cudaStreamWaitEvent(0, evFill, 0);
    kernel_combine<<<dim3(U_, BH_PER_Q), 64>>>(out, 3 * BH_PER_Q);

    // join s2 back into main before returning
    cudaEventRecord(evJoin, s2);
    cudaStreamWaitEvent(0, evJoin, 0);
}

// round 14
// speedup vs baseline: 1.5961x; 1.1893x over previous
#include <cuda_runtime.h>
#include <math_constants.h>

// ProbAttention: B=4, L=4096, H=8, D=64, FACTOR=5
#define B_ 4
#define L_ 4096
#define H_ 8
#define D_ 64
#define SK_ 45
#define U_  45
#define NSPLIT 64
#define KC 64          // keys per split = L_/NSPLIT
#define PADK 68

// Scratch (device globals; no allocation allowed)
__device__ float g_M[B_ * H_ * L_];
__device__ int   g_Mtop[B_ * H_ * U_];
__device__ float g_vmean[B_ * H_ * D_];
__device__ float g_pm[B_ * H_ * NSPLIT * U_];
__device__ float g_ps[B_ * H_ * NSPLIT * U_];
__device__ float g_pacc[B_ * H_ * NSPLIT * U_ * D_];   // 23.6 MB

typedef unsigned long long ull;
__device__ __forceinline__ float lo2(ull v) { return __uint_as_float((unsigned)v); }
__device__ __forceinline__ float hi2(ull v) { return __uint_as_float((unsigned)(v >> 32)); }
#define FMA2(acc, a, b) asm("fma.rn.f32x2 %0, %1, %2, %0;" : "+l"(acc) : "l"(a), "l"(b))
#define DUP2(out, x) asm("mov.b64 %0, {%1, %1};" : "=l"(out) : "r"(__float_as_uint(x)))

__device__ __forceinline__ unsigned smem_u32(const void* p) {
    return (unsigned)__cvta_generic_to_shared(p);
}

// ---------------------------------------------------------------------------
// Kernel 1: M scores — monolithic gather kernel, AT the LTS cap (127us).
// Do not fragment this grid (R13 showed quartering costs ~16%).
// ---------------------------------------------------------------------------
__global__ void __launch_bounds__(256) kernel_M(const float* __restrict__ Q,
                                                const float* __restrict__ K,
                                                const int* __restrict__ idx) {
    int j = (blockIdx.x * 111) & 16383;      // bijective remap
    int w = j * 8 + (threadIdx.x >> 5);
    int lane = threadIdx.x & 31;
    int li = lane & 7;
    int g  = lane >> 3;
    int l = w & (L_ - 1);
    int h = (w >> 12) & (H_ - 1);
    int b = w >> 15;

    const float4* q4 = (const float4*)(Q + ((b * L_ + l) * H_ + h) * D_);
    float4 qa = q4[li * 2];
    float4 qb = q4[li * 2 + 1];

    const int* ip = idx + l * SK_;
    float mx = -CUDART_INF_F;
    float sm = 0.0f;
#pragma unroll
    for (int sg = 0; sg < 12; sg++) {
        int s = sg * 4 + g;
        bool valid = (s < SK_);
        int kr = ip[valid ? s : 0];
        const float4* k4 = (const float4*)(K + ((b * L_ + kr) * H_ + h) * D_);
        float4 ka = k4[li * 2];
        float4 kb = k4[li * 2 + 1];
        float d = qa.x * ka.x + qa.y * ka.y + qa.z * ka.z + qa.w * ka.w
                + qb.x * kb.x + qb.y * kb.y + qb.z * kb.z + qb.w * kb.w;
        d += __shfl_xor_sync(0xffffffffu, d, 4);
        d += __shfl_xor_sync(0xffffffffu, d, 2);
        d += __shfl_xor_sync(0xffffffffu, d, 1);
        if (valid) { mx = fmaxf(mx, d); sm += d; }
    }
    mx = fmaxf(mx, __shfl_xor_sync(0xffffffffu, mx, 8));
    mx = fmaxf(mx, __shfl_xor_sync(0xffffffffu, mx, 16));
    sm += __shfl_xor_sync(0xffffffffu, sm, 8);
    sm += __shfl_xor_sync(0xffffffffu, sm, 16);
    if (lane == 0) g_M[w] = mx - sm * (1.0f / (float)L_);
}

// ---------------------------------------------------------------------------
// Kernel 2: top-U per (b,h): two-level radix histogram + exact tail select.
// ---------------------------------------------------------------------------
__device__ __forceinline__ unsigned f2key(float f) {
    unsigned u = __float_as_uint(f);
    return (u & 0x80000000u) ? ~u : (u | 0x80000000u);
}

__global__ void __launch_bounds__(256) kernel_topk() {
    __shared__ unsigned skeys[L_];
    __shared__ int hist[256];
    __shared__ unsigned candKey[1024];
    __shared__ int candIdx[1024];
    __shared__ int sT1, sN1, sT2;
    __shared__ int cSel, cCand;
    __shared__ unsigned rk[256];
    __shared__ int ri[256];

    int bh = blockIdx.x;
    int t = threadIdx.x;
    const float* m = g_M + bh * L_;
    for (int i = t; i < L_; i += 256) skeys[i] = f2key(m[i]);
    hist[t] = 0;
    __syncthreads();

    for (int i = t; i < L_; i += 256) atomicAdd(&hist[skeys[i] >> 24], 1);
    __syncthreads();
    if (t == 0) {
        int acc = 0;
        for (int bin = 255; bin >= 0; bin--) {
            if (acc + hist[bin] >= U_) { sT1 = bin; sN1 = acc; break; }
            acc += hist[bin];
        }
    }
    __syncthreads();
    int T1 = sT1, n1 = sN1;
    hist[t] = 0;
    __syncthreads();

    for (int i = t; i < L_; i += 256)
        if ((int)(skeys[i] >> 24) == T1) atomicAdd(&hist[(skeys[i] >> 16) & 255], 1);
    __syncthreads();
    if (t == 0) {
        int acc = n1;
        for (int bin = 255; bin >= 0; bin--) {
            if (acc + hist[bin] >= U_) { sT2 = bin; break; }
            acc += hist[bin];
        }
        cSel = 0; cCand = 0;
    }
    __syncthreads();
    unsigned TH16 = ((unsigned)T1 << 8) | (unsigned)sT2;

    for (int i = t; i < L_; i += 256) {
        unsigned k16 = skeys[i] >> 16;
        if (k16 > TH16) {
            int pos = atomicAdd(&cSel, 1);
            g_Mtop[bh * U_ + pos] = i;
        } else if (k16 == TH16) {
            int pos = atomicAdd(&cCand, 1);
            if (pos < 1024) { candKey[pos] = skeys[i]; candIdx[pos] = i; }
        }
    }
    __syncthreads();
    int ndef = cSel;
    int need = U_ - ndef;
    int nc = (cCand < 1024) ? cCand : 1024;

    for (int it = 0; it < need; it++) {
        unsigned best = 0; int bi = -1;
        for (int jj = t; jj < nc; jj += 256) {
            unsigned v = candKey[jj];
            if (v > best) { best = v; bi = jj; }
        }
        rk[t] = best; ri[t] = bi;
        __syncthreads();
        for (int s = 128; s; s >>= 1) {
            if (t < s && rk[t + s] > rk[t]) { rk[t] = rk[t + s]; ri[t] = ri[t + s]; }
            __syncthreads();
        }
        if (t == 0) {
            g_Mtop[bh * U_ + ndef + it] = candIdx[ri[0]];
            candKey[ri[0]] = 0;
        }
        __syncthreads();
    }
}

// ---------------------------------------------------------------------------
// Kernel 3: V mean (zero + float4 partial sums)
// ---------------------------------------------------------------------------
__global__ void kernel_zero_mean() {
    int i = blockIdx.x * blockDim.x + threadIdx.x;
    if (i < B_ * H_ * D_) g_vmean[i] = 0.0f;
}

__global__ void __launch_bounds__(256) kernel_mean_part(const float* __restrict__ V) {
    int blk = blockIdx.x;              // 1024 blocks
    int seg = blk & 31;
    int bh = blk >> 5;
    int h = bh & (H_ - 1);
    int b = bh >> 3;
    int t = threadIdx.x;
    int d4 = t & 15;
    int sub = t >> 4;
    int l0 = seg * 128;
    const float4* V4 = (const float4*)V;
    float ax = 0.f, ay = 0.f, az = 0.f, aw = 0.f;
#pragma unroll
    for (int i = 0; i < 8; i++) {
        int l = l0 + sub + i * 16;
        float4 v = V4[((size_t)(b * L_ + l) * H_ + h) * 16 + d4];
        ax += v.x; ay += v.y; az += v.z; aw += v.w;
    }
    __shared__ float4 s[16][16];
    s[sub][d4] = make_float4(ax, ay, az, aw);
    __syncthreads();
    if (t < 16) {
        float tx = 0.f, ty = 0.f, tz = 0.f, tw = 0.f;
#pragma unroll
        for (int jj = 0; jj < 16; jj++) {
            float4 v = s[jj][t];
            tx += v.x; ty += v.y; tz += v.z; tw += v.w;
        }
        atomicAdd(&g_vmean[bh * D_ + t * 4 + 0], tx);
        atomicAdd(&g_vmean[bh * D_ + t * 4 + 1], ty);
        atomicAdd(&g_vmean[bh * D_ + t * 4 + 2], tz);
        atomicAdd(&g_vmean[bh * D_ + t * 4 + 3], tw);
    }
}

// ---------------------------------------------------------------------------
// Kernel 4: fill out with V-mean broadcast (float4 stores)
// ---------------------------------------------------------------------------
__global__ void kernel_fill(float* __restrict__ out) {
    unsigned i = blockIdx.x * blockDim.x + threadIdx.x;  // float4 index
    int d4 = i & 15;
    int h = (i >> 4) & 7;
    int b = i >> 19;
    const float4* vm4 = (const float4*)g_vmean;
    float4 v = vm4[(b * H_ + h) * 16 + d4];
    const float inv = 1.0f / (float)L_;
    ((float4*)out)[i] = make_float4(v.x * inv, v.y * inv, v.z * inv, v.w * inv);
}

// ---------------------------------------------------------------------------
// Kernel 5: split-KV attention (NSPLIT=64, KC=64) with float4 q/e loads:
// per 4-d block phase 1 issues 3 LDS.128 (q) + 4 LDS.128 (K) instead of
// 12 LDS.32 + 4 LDS.128 — 56% fewer LSU slots. Same math, same layout.
// ---------------------------------------------------------------------------
#define OFF_V   (64 * PADK)
#define OFF_QE  (OFF_V + 64 * PADK)
#define OFF_MT  (OFF_QE + 48 * 64)
#define SMEM_FLOATS (OFF_MT + 64)
#define SMEM_BYTES  (SMEM_FLOATS * 4)

__global__ void __launch_bounds__(256) kernel_attn_part(
        const float* __restrict__ Q,
        const float* __restrict__ K,
        const float* __restrict__ V) {
    extern __shared__ float smem[];
    float* sKT = smem;                  // [64][PADK]  K transposed [d][k]
    float* sV  = smem + OFF_V;          // [64][PADK]  V natural   [k][d]
    float* sQE = smem + OFF_QE;         // [48][64]    Q rows, then E rows
    int*   sMt = (int*)(smem + OFF_MT);

    int bh = blockIdx.x >> 6;
    int sp = blockIdx.x & 63;
    int h = bh & 7, b = bh >> 3;
    int k0 = sp * KC;
    int t = threadIdx.x;

    {
        const char* vbase = (const char*)(V + ((size_t)(b * L_ + k0) * H_ + h) * D_);
#pragma unroll
        for (int i = 0; i < 4; i++) {
            int e = t + i * 256;
            int row = e >> 4, c = e & 15;
            unsigned dst = smem_u32(sV + row * PADK + c * 4);
            const char* src = vbase + (size_t)row * (H_ * D_ * 4) + c * 16;
            asm volatile("cp.async.cg.shared.global [%0], [%1], 16;"
                         :: "r"(dst), "l"(src));
        }
        asm volatile("cp.async.commit_group;");
    }

    if (t < U_) sMt[t] = g_Mtop[bh * U_ + t];
    __syncthreads();

#pragma unroll
    for (int i = 0; i < 3; i++) {
        int e = t + i * 256;
        int u = e >> 4, c = e & 15;
        float4 q = make_float4(0.f, 0.f, 0.f, 0.f);
        if (u < U_)
            q = *(const float4*)(Q + ((b * L_ + sMt[u]) * H_ + h) * D_ + c * 4);
        *(float4*)(sQE + u * 64 + c * 4) = q;
    }
#pragma unroll
    for (int i = 0; i < 16; i++) {
        int e = t + i * 256;
        int k = e >> 6, d = e & 63;
        sKT[d * PADK + k] = K[((b * L_ + k0 + k) * H_ + h) * D_ + d];
    }
    __syncthreads();

    int kt = t & 15, ut = t >> 4;
    int kk = kt * 4, u0 = ut * 3;

    ull a00 = 0, a01 = 0, a10 = 0, a11 = 0, a20 = 0, a21 = 0;
    {
        const float* q0p = sQE + (u0 + 0) * 64;
        const float* q1p = sQE + (u0 + 1) * 64;
        const float* q2p = sQE + (u0 + 2) * 64;
#pragma unroll 4
        for (int d = 0; d < 64; d += 4) {
            float4 f0 = *(const float4*)(q0p + d);
            float4 f1 = *(const float4*)(q1p + d);
            float4 f2 = *(const float4*)(q2p + d);
#pragma unroll
            for (int j = 0; j < 4; j++) {
                ulonglong2 kv = *(const ulonglong2*)&sKT[(d + j) * PADK + kk];
                float w0 = (j == 0) ? f0.x : (j == 1) ? f0.y : (j == 2) ? f0.z : f0.w;
                float w1 = (j == 0) ? f1.x : (j == 1) ? f1.y : (j == 2) ? f1.z : f1.w;
                float w2 = (j == 0) ? f2.x : (j == 1) ? f2.y : (j == 2) ? f2.z : f2.w;
                ull q0, q1, q2;
                DUP2(q0, w0); DUP2(q1, w1); DUP2(q2, w2);
                FMA2(a00, q0, kv.x); FMA2(a01, q0, kv.y);
                FMA2(a10, q1, kv.x); FMA2(a11, q1, kv.y);
                FMA2(a20, q2, kv.x); FMA2(a21, q2, kv.y);
            }
        }
    }

    float ev[3][4];
    {
        const float sc = 0.125f;
        ull ra[3][2] = {{a00, a01}, {a10, a11}, {a20, a21}};
#pragma unroll
        for (int jj = 0; jj < 3; jj++) {
            float s0 = lo2(ra[jj][0]) * sc, s1 = hi2(ra[jj][0]) * sc;
            float s2 = lo2(ra[jj][1]) * sc, s3 = hi2(ra[jj][1]) * sc;
            float mm = fmaxf(fmaxf(s0, s1), fmaxf(s2, s3));
            mm = fmaxf(mm, __shfl_xor_sync(0xffffffffu, mm, 1));
            mm = fmaxf(mm, __shfl_xor_sync(0xffffffffu, mm, 2));
            mm = fmaxf(mm, __shfl_xor_sync(0xffffffffu, mm, 4));
            mm = fmaxf(mm, __shfl_xor_sync(0xffffffffu, mm, 8));
            float e0 = __expf(s0 - mm), e1 = __expf(s1 - mm);
            float e2 = __expf(s2 - mm), e3 = __expf(s3 - mm);
            float ss = (e0 + e1) + (e2 + e3);
            ss += __shfl_xor_sync(0xffffffffu, ss, 1);
            ss += __shfl_xor_sync(0xffffffffu, ss, 2);
            ss += __shfl_xor_sync(0xffffffffu, ss, 4);
            ss += __shfl_xor_sync(0xffffffffu, ss, 8);
            ev[jj][0] = e0; ev[jj][1] = e1; ev[jj][2] = e2; ev[jj][3] = e3;
            int u = u0 + jj;
            if (kt == 0 && u < U_) {
                g_pm[(bh * NSPLIT + sp) * U_ + u] = mm;
                g_ps[(bh * NSPLIT + sp) * U_ + u] = ss;
            }
        }
    }
    __syncthreads();

#pragma unroll
    for (int jj = 0; jj < 3; jj++)
        *(float4*)(sQE + (u0 + jj) * 64 + kk) =
            make_float4(ev[jj][0], ev[jj][1], ev[jj][2], ev[jj][3]);

    asm volatile("cp.async.wait_group 0;");
    __syncthreads();

    {
        int dd = kk;
        ull c00 = 0, c01 = 0, c10 = 0, c11 = 0, c20 = 0, c21 = 0;
        const float* e0p = sQE + (u0 + 0) * 64;
        const float* e1p = sQE + (u0 + 1) * 64;
        const float* e2p = sQE + (u0 + 2) * 64;
#pragma unroll 4
        for (int k = 0; k < 64; k += 4) {
            float4 f0 = *(const float4*)(e0p + k);
            float4 f1 = *(const float4*)(e1p + k);
            float4 f2 = *(const float4*)(e2p + k);
#pragma unroll
            for (int j = 0; j < 4; j++) {
                ulonglong2 vv = *(const ulonglong2*)&sV[(k + j) * PADK + dd];
                float w0 = (j == 0) ? f0.x : (j == 1) ? f0.y : (j == 2) ? f0.z : f0.w;
                float w1 = (j == 0) ? f1.x : (j == 1) ? f1.y : (j == 2) ? f1.z : f1.w;
                float w2 = (j == 0) ? f2.x : (j == 1) ? f2.y : (j == 2) ? f2.z : f2.w;
                ull e0, e1, e2;
                DUP2(e0, w0); DUP2(e1, w1); DUP2(e2, w2);
                FMA2(c00, e0, vv.x); FMA2(c01, e0, vv.y);
                FMA2(c10, e1, vv.x); FMA2(c11, e1, vv.y);
                FMA2(c20, e2, vv.x); FMA2(c21, e2, vv.y);
            }
        }
        float* pa = g_pacc + (size_t)(bh * NSPLIT + sp) * U_ * D_;
        if (u0 + 0 < U_)
            *(float4*)&pa[(u0 + 0) * D_ + dd] =
                make_float4(lo2(c00), hi2(c00), lo2(c01), hi2(c01));
        if (u0 + 1 < U_)
            *(float4*)&pa[(u0 + 1) * D_ + dd] =
                make_float4(lo2(c10), hi2(c10), lo2(c11), hi2(c11));
        if (u0 + 2 < U_)
            *(float4*)&pa[(u0 + 2) * D_ + dd] =
                make_float4(lo2(c20), hi2(c20), lo2(c21), hi2(c21));
    }
}

// ---------------------------------------------------------------------------
// Kernel 6: combine partials. grid = (U_, B*H), 64 threads.
// ---------------------------------------------------------------------------
__global__ void __launch_bounds__(64) kernel_combine(float* __restrict__ out) {
    __shared__ float sw[NSPLIT];
    __shared__ float red[64];
    int u = blockIdx.x;
    int bh = blockIdx.y;
    int h = bh & 7, b = bh >> 3;
    int t = threadIdx.x;

    float m = g_pm[(bh * NSPLIT + t) * U_ + u];
    float s = g_ps[(bh * NSPLIT + t) * U_ + u];
    red[t] = m;
    __syncthreads();
    for (int st = 32; st; st >>= 1) {
        if (t < st) red[t] = fmaxf(red[t], red[t + st]);
        __syncthreads();
    }
    float M = red[0];
    __syncthreads();
    float e = __expf(m - M);
    red[t] = e * s;
    __syncthreads();
    for (int st = 32; st; st >>= 1) {
        if (t < st) red[t] += red[t + st];
        __syncthreads();
    }
    float inv = 1.0f / red[0];
    sw[t] = e * inv;
    __syncthreads();

    float acc = 0.0f;
    const float* pa = g_pacc + (size_t)bh * NSPLIT * U_ * D_ + u * D_ + t;
#pragma unroll 8
    for (int sp = 0; sp < NSPLIT; sp++)
        acc += pa[(size_t)sp * U_ * D_] * sw[sp];
    int lsel = g_Mtop[bh * U_ + u];
    out[((b * L_ + lsel) * H_ + h) * D_ + t] = acc;
}

// ---------------------------------------------------------------------------
// Launch (R10 structure, measured 209.2us): main = M, topk, attn, combine;
// side s2 = zero, mean, fill overlapped under M; join before combine.
// ---------------------------------------------------------------------------
extern "C" void kernel_launch(void* const* d_in, const int* in_sizes, int n_in,
                              void* d_out, int out_size) {
    const float* Q = (const float*)d_in[0];
    const float* K = (const float*)d_in[1];
    const float* V = (const float*)d_in[2];
    const int* idx = (const int*)d_in[3];   // int32 (JAX x64 disabled)
    float* out = (float*)d_out;

    static cudaStream_t s2 = nullptr;
    static cudaEvent_t evFork = nullptr, evJoin = nullptr;
    if (s2 == nullptr) {
        cudaStreamCreateWithFlags(&s2, cudaStreamNonBlocking);
        cudaEventCreateWithFlags(&evFork, cudaEventDisableTiming);
        cudaEventCreateWithFlags(&evJoin, cudaEventDisableTiming);
        cudaFuncSetAttribute((const void*)kernel_M,
                             cudaFuncAttributePreferredSharedMemoryCarveout, 0);
        cudaFuncSetAttribute((const void*)kernel_attn_part,
                             cudaFuncAttributeMaxDynamicSharedMemorySize, SMEM_BYTES);
    }

    // Fork side stream off the (possibly capturing) legacy stream.
    cudaEventRecord(evFork, 0);
    cudaStreamWaitEvent(s2, evFork, 0);

    // Main chain (submissions 1,2; slot-4 ncu capture lands on attn below)
    kernel_M<<<(B_ * H_ * L_) / 8, 256>>>(Q, K, idx);
    kernel_topk<<<B_ * H_, 256>>>();

    // Side chain on s2 (runs concurrently with kernel_M)
    kernel_zero_mean<<<(B_ * H_ * D_ + 255) / 256, 256, 0, s2>>>();

    // submission 4: attn (main chain)
    kernel_attn_part<<<B_ * H_ * NSPLIT, 256, SMEM_BYTES>>>(Q, K, V);

    kernel_mean_part<<<B_ * H_ * 32, 256, 0, s2>>>(V);
    kernel_fill<<<(B_ * L_ * H_ * D_ / 4 + 255) / 256, 256, 0, s2>>>(out);

    // Join side stream back, then combine (needs pacc + fill-complete).
    cudaEventRecord(evJoin, s2);
    cudaStreamWaitEvent(0, evJoin, 0);
    kernel_combine<<<dim3(U_, B_ * H_), 64>>>(out);
}